// round 15
// baseline (speedup 1.0000x reference)
#include <cuda_runtime.h>
#include <cuda_bf16.h>
#include <mma.h>
#include <math.h>
#include <cstdint>

using namespace nvcuda;

#define BB 2
#define SS 2048
#define DD 1024
#define HH 16
#define KHH 4
#define DKK 64
#define REP 4
#define NQKV 1536   // 1024 Q | 256 K | 256 V

// fp32 scratch
__device__ float g_cos[SS * 32];
__device__ float g_sin[SS * 32];
__device__ float g_bqkv[NQKV];

// bf16 split scratch
__device__ __nv_bfloat16 g_xhi[BB * SS * DD],    g_xlo[BB * SS * DD];
__device__ __nv_bfloat16 g_ohi[BB * SS * DD],    g_olo[BB * SS * DD];
__device__ __nv_bfloat16 g_wqkvhi[DD * NQKV],    g_wqkvlo[DD * NQKV];
__device__ __nv_bfloat16 g_wohi[DD * DD],        g_wolo[DD * DD];
__device__ __nv_bfloat16 g_qkvhi[BB * SS * NQKV], g_qkvlo[BB * SS * NQKV];

// ---------------------------------------------------------------------------
// cp.async helpers
// ---------------------------------------------------------------------------
__device__ __forceinline__ void cp_async16(void* sptr, const void* gptr) {
    unsigned int s = (unsigned int)__cvta_generic_to_shared(sptr);
    asm volatile("cp.async.cg.shared.global [%0], [%1], 16;\n" :: "r"(s), "l"(gptr));
}
__device__ __forceinline__ void cp_commit() { asm volatile("cp.async.commit_group;\n"); }
__device__ __forceinline__ void cp_wait1() { asm volatile("cp.async.wait_group 1;\n"); }
__device__ __forceinline__ void cp_wait0() { asm volatile("cp.async.wait_group 0;\n"); }

// ---------------------------------------------------------------------------
// Small kernels
// ---------------------------------------------------------------------------
__global__ void split_kernel(const float* __restrict__ in,
                             __nv_bfloat16* __restrict__ hi,
                             __nv_bfloat16* __restrict__ lo, int n) {
    int i = blockIdx.x * blockDim.x + threadIdx.x;
    if (i >= n) return;
    float f = in[i];
    __nv_bfloat16 h = __float2bfloat16(f);
    hi[i] = h;
    lo[i] = __float2bfloat16(f - __bfloat162float(h));
}

__global__ void pack_wqkv_kernel(const float* __restrict__ Wq, const float* __restrict__ Wk,
                                 const float* __restrict__ Wv, const float* __restrict__ bq,
                                 const float* __restrict__ bk, const float* __restrict__ bv,
                                 __nv_bfloat16* __restrict__ hi, __nv_bfloat16* __restrict__ lo,
                                 float* __restrict__ bqkv) {
    int i = blockIdx.x * blockDim.x + threadIdx.x;
    int n = DD * NQKV;
    if (i < NQKV) {
        int c = i;
        bqkv[c] = (c < 1024) ? bq[c] : (c < 1280 ? bk[c - 1024] : bv[c - 1280]);
    }
    if (i >= n) return;
    int row = i / NQKV;
    int col = i % NQKV;
    float f;
    if (col < 1024)      f = Wq[row * 1024 + col];
    else if (col < 1280) f = Wk[row * 256 + col - 1024];
    else                 f = Wv[row * 256 + col - 1280];
    __nv_bfloat16 h = __float2bfloat16(f);
    hi[i] = h;
    lo[i] = __float2bfloat16(f - __bfloat162float(h));
}

__global__ void rope_table_kernel(float* __restrict__ ctab, float* __restrict__ stab) {
    int idx = blockIdx.x * blockDim.x + threadIdx.x;
    if (idx >= SS * 32) return;
    int s = idx >> 5;
    int d = idx & 31;
    double theta = pow(10000.0, -(double)d / 32.0);
    double f = (double)s * theta;
    ctab[idx] = (float)cos(f);
    stab[idx] = (float)sin(f);
}

// ---------------------------------------------------------------------------
// Shared GEMM config (v4 mainloop): 128x128 block, 128 threads = 4 warps
// (2m x 2n), warp tile 64x64, BK=32 double-buffered cp.async, 2 CTAs/SM.
// ---------------------------------------------------------------------------
#define GSM_A_BYTES (2 * 2 * 128 * 40 * 2)
#define GSM_B_BYTES (2 * 2 * 32 * 136 * 2)
#define GSM_TOTAL (GSM_A_BYTES + GSM_B_BYTES)

__device__ __forceinline__ int sA_idx(int buf, int part, int r, int c) {
    return ((buf * 2 + part) * 128 + r) * 40 + c;
}
__device__ __forceinline__ int sB_idx(int buf, int part, int r, int c) {
    return ((buf * 2 + part) * 32 + r) * 136 + c;
}

struct GemmCtx {
    const __nv_bfloat16 *Ahi, *Alo, *Bhi, *Blo;
    int M, N, K, m0, n0, tid;
    __nv_bfloat16 *sA, *sB;
};

__device__ __forceinline__ void gemm_mainloop(
    GemmCtx& g, wmma::fragment<wmma::accumulator, 16, 16, 16, float> (&acc)[4][4],
    int wm, int wn) {
    const int nk = g.K / 32;
    auto load_stage = [&](int buf, int k0) {
#pragma unroll
        for (int t = g.tid; t < 1024; t += 128) {
            int part = t >> 9;
            int c = t & 511;
            int r = c >> 2;
            int cc = (c & 3) * 8;
            size_t gm = (size_t)(g.m0 + r) * g.K + k0 + cc;
            cp_async16(&g.sA[sA_idx(buf, part, r, cc)], part ? &g.Alo[gm] : &g.Ahi[gm]);
        }
#pragma unroll
        for (int t = g.tid; t < 1024; t += 128) {
            int part = t >> 9;
            int c = t & 511;
            int r = c >> 4;
            int cc = (c & 15) * 8;
            size_t gm = (size_t)(k0 + r) * g.N + g.n0 + cc;
            cp_async16(&g.sB[sB_idx(buf, part, r, cc)], part ? &g.Blo[gm] : &g.Bhi[gm]);
        }
        cp_commit();
    };

    load_stage(0, 0);

    for (int kt = 0; kt < nk; kt++) {
        int buf = kt & 1;
        if (kt + 1 < nk) {
            load_stage(buf ^ 1, (kt + 1) * 32);
            cp_wait1();
        } else {
            cp_wait0();
        }
        __syncthreads();

#pragma unroll
        for (int ks = 0; ks < 2; ks++) {
            wmma::fragment<wmma::matrix_a, 16, 16, 16, __nv_bfloat16, wmma::row_major> ahi[4], alo[4];
#pragma unroll
            for (int i = 0; i < 4; i++) {
                wmma::load_matrix_sync(ahi[i], &g.sA[sA_idx(buf, 0, wm * 64 + i * 16, ks * 16)], 40);
                wmma::load_matrix_sync(alo[i], &g.sA[sA_idx(buf, 1, wm * 64 + i * 16, ks * 16)], 40);
            }
#pragma unroll
            for (int j = 0; j < 4; j++) {
                wmma::fragment<wmma::matrix_b, 16, 16, 16, __nv_bfloat16, wmma::row_major> bhi, blo;
                wmma::load_matrix_sync(bhi, &g.sB[sB_idx(buf, 0, ks * 16, wn * 64 + j * 16)], 136);
                wmma::load_matrix_sync(blo, &g.sB[sB_idx(buf, 1, ks * 16, wn * 64 + j * 16)], 136);
#pragma unroll
                for (int i = 0; i < 4; i++) {
                    wmma::mma_sync(acc[i][j], ahi[i], bhi, acc[i][j]);
                    wmma::mma_sync(acc[i][j], ahi[i], blo, acc[i][j]);
                    wmma::mma_sync(acc[i][j], alo[i], bhi, acc[i][j]);
                }
            }
        }
        __syncthreads();
    }
}

// ---------------------------------------------------------------------------
// QKV GEMM with fused bias + RoPE + bf16 hi/lo split epilogue. m_off selects
// the batch's row range so the two batches run on separate streams.
// ---------------------------------------------------------------------------
__global__ __launch_bounds__(128, 2)
void gemm_qkv_rope(const __nv_bfloat16* __restrict__ Ahi,
                   const __nv_bfloat16* __restrict__ Alo,
                   const __nv_bfloat16* __restrict__ Bhi,
                   const __nv_bfloat16* __restrict__ Blo,
                   const float* __restrict__ bias,
                   const float* __restrict__ ctab,
                   const float* __restrict__ stab,
                   __nv_bfloat16* __restrict__ ohi,
                   __nv_bfloat16* __restrict__ olo,
                   int M, int N, int K, int m_off) {
    extern __shared__ __align__(16) unsigned char smraw[];
    GemmCtx g;
    g.Ahi = Ahi; g.Alo = Alo; g.Bhi = Bhi; g.Blo = Blo;
    g.M = M; g.N = N; g.K = K;
    g.tid = threadIdx.x;
    g.m0 = m_off + blockIdx.y * 128;
    g.n0 = blockIdx.x * 128;
    g.sA = (__nv_bfloat16*)smraw;
    g.sB = (__nv_bfloat16*)(smraw + GSM_A_BYTES);

    const int warp = threadIdx.x >> 5;
    const int lane = threadIdx.x & 31;
    const int wm = warp >> 1;
    const int wn = warp & 1;

    wmma::fragment<wmma::accumulator, 16, 16, 16, float> acc[4][4];
#pragma unroll
    for (int i = 0; i < 4; i++)
#pragma unroll
        for (int j = 0; j < 4; j++) wmma::fill_fragment(acc[i][j], 0.0f);

    gemm_mainloop(g, acc, wm, wn);

    float* stg = (float*)(smraw) + warp * (64 * 68);
#pragma unroll
    for (int i = 0; i < 4; i++)
#pragma unroll
        for (int j = 0; j < 4; j++)
            wmma::store_matrix_sync(&stg[(i * 16) * 68 + j * 16], acc[i][j], 68,
                                    wmma::mem_row_major);
    __syncwarp();

    const int col_base = g.n0 + wn * 64;
    const int row_base = g.m0 + wm * 64;

    if (col_base < 1280) {
        for (int t = lane; t < 2048; t += 32) {
            int r = t >> 5;
            int d = t & 31;
            float x1 = stg[r * 68 + d] + bias[col_base + d];
            float x2 = stg[r * 68 + d + 32] + bias[col_base + d + 32];
            int grow = row_base + r;
            int s = grow & (SS - 1);
            float c = ctab[s * 32 + d];
            float sn = stab[s * 32 + d];
            float r1 = x1 * c - x2 * sn;
            float r2 = x2 * c + x1 * sn;
            size_t base = (size_t)grow * NQKV + col_base + d;
            __nv_bfloat16 h1 = __float2bfloat16(r1);
            __nv_bfloat16 h2 = __float2bfloat16(r2);
            ohi[base] = h1;
            olo[base] = __float2bfloat16(r1 - __bfloat162float(h1));
            ohi[base + 32] = h2;
            olo[base + 32] = __float2bfloat16(r2 - __bfloat162float(h2));
        }
    } else {
        for (int t = lane; t < 4096; t += 32) {
            int r = t >> 6;
            int d = t & 63;
            float f = stg[r * 68 + d] + bias[col_base + d];
            size_t base = (size_t)(row_base + r) * NQKV + col_base + d;
            __nv_bfloat16 h = __float2bfloat16(f);
            ohi[base] = h;
            olo[base] = __float2bfloat16(f - __bfloat162float(h));
        }
    }
}

// ---------------------------------------------------------------------------
// Output-projection GEMM with fused bias epilogue (fp32 out, m_off for batch)
// ---------------------------------------------------------------------------
__global__ __launch_bounds__(128, 2)
void gemm_out_bias(const __nv_bfloat16* __restrict__ Ahi,
                   const __nv_bfloat16* __restrict__ Alo,
                   const __nv_bfloat16* __restrict__ Bhi,
                   const __nv_bfloat16* __restrict__ Blo,
                   const float* __restrict__ bias,
                   float* __restrict__ C, int M, int N, int K, int m_off) {
    extern __shared__ __align__(16) unsigned char smraw[];
    GemmCtx g;
    g.Ahi = Ahi; g.Alo = Alo; g.Bhi = Bhi; g.Blo = Blo;
    g.M = M; g.N = N; g.K = K;
    g.tid = threadIdx.x;
    g.m0 = m_off + blockIdx.y * 128;
    g.n0 = blockIdx.x * 128;
    g.sA = (__nv_bfloat16*)smraw;
    g.sB = (__nv_bfloat16*)(smraw + GSM_A_BYTES);

    const int warp = threadIdx.x >> 5;
    const int lane = threadIdx.x & 31;
    const int wm = warp >> 1;
    const int wn = warp & 1;

    wmma::fragment<wmma::accumulator, 16, 16, 16, float> acc[4][4];
#pragma unroll
    for (int i = 0; i < 4; i++)
#pragma unroll
        for (int j = 0; j < 4; j++) wmma::fill_fragment(acc[i][j], 0.0f);

    gemm_mainloop(g, acc, wm, wn);

    float* stg = (float*)(smraw) + warp * (64 * 68);
#pragma unroll
    for (int i = 0; i < 4; i++)
#pragma unroll
        for (int j = 0; j < 4; j++)
            wmma::store_matrix_sync(&stg[(i * 16) * 68 + j * 16], acc[i][j], 68,
                                    wmma::mem_row_major);
    __syncwarp();

    const int col_base = g.n0 + wn * 64;
    const int row_base = g.m0 + wm * 64;
    for (int t = lane; t < 4096; t += 32) {
        int r = t >> 6;
        int d = t & 63;
        C[(size_t)(row_base + r) * g.N + col_base + d] =
            stg[r * 68 + d] + bias[col_base + d];
    }
}

// ---------------------------------------------------------------------------
// flash_tc_v3 (R10-known-good), batch passed as parameter for stream split.
// ---------------------------------------------------------------------------
#define F3_QHI 0
#define F3_QLO 18432
#define F3_KHI 36864
#define F3_KLO 46080
#define F3_VHI 55296
#define F3_VLO 64512
#define F3_SFP 73728
#define F3_PHI 73728
#define F3_PLO 92160
#define F3_M   110592
#define F3_L   111104
#define F3_AL  111616
#define F3_SMEM_TOTAL 112128

__global__ __launch_bounds__(256, 2)
void flash_tc_v3(const __nv_bfloat16* __restrict__ qh,
                 const __nv_bfloat16* __restrict__ ql,
                 __nv_bfloat16* __restrict__ ohi,
                 __nv_bfloat16* __restrict__ olo, int b) {
    extern __shared__ __align__(16) unsigned char fsm[];
    __nv_bfloat16* Qhi = (__nv_bfloat16*)(fsm + F3_QHI);
    __nv_bfloat16* Qlo = (__nv_bfloat16*)(fsm + F3_QLO);
    __nv_bfloat16* Khi = (__nv_bfloat16*)(fsm + F3_KHI);
    __nv_bfloat16* Klo = (__nv_bfloat16*)(fsm + F3_KLO);
    __nv_bfloat16* Vhi = (__nv_bfloat16*)(fsm + F3_VHI);
    __nv_bfloat16* Vlo = (__nv_bfloat16*)(fsm + F3_VLO);
    float* Sf  = (float*)(fsm + F3_SFP);
    __nv_bfloat16* Phi = (__nv_bfloat16*)(fsm + F3_PHI);
    __nv_bfloat16* Plo = (__nv_bfloat16*)(fsm + F3_PLO);
    float* m_sh = (float*)(fsm + F3_M);
    float* l_sh = (float*)(fsm + F3_L);
    float* al_sh= (float*)(fsm + F3_AL);

    const int tid = threadIdx.x;
    const int warp = tid >> 5;
    const int qt = (int)gridDim.x - 1 - (int)blockIdx.x;
    const int kh = blockIdx.y >> 1;
    const int pair = blockIdx.y & 1;
    const int s0q = qt * 64;
    const int m0w = warp * 16;

    __nv_bfloat16* kvdst[4] = {Khi, Klo, Vhi, Vlo};
    auto load_kv = [&](int s0k) {
        for (int t = tid; t < 2048; t += 256) {
            int arr = t >> 9;
            int r = (t >> 3) & 63;
            int ch = (t & 7) * 8;
            const __nv_bfloat16* src = (arr & 1) ? ql : qh;
            size_t g = (size_t)(b * SS + s0k + r) * NQKV + 1024 + kh * 64 +
                       ((arr >> 1) ? 256 : 0) + ch;
            cp_async16(&kvdst[arr][r * 72 + ch], &src[g]);
        }
        cp_commit();
    };

    load_kv(0);

    for (int t = tid; t < 2048; t += 256) {
        int part = t >> 10;
        int m = (t >> 3) & 127;
        int ch = (t & 7) * 8;
        int hp = m >> 6;
        int rr = m & 63;
        const __nv_bfloat16* src = part ? ql : qh;
        size_t gaddr = (size_t)(b * SS + s0q + rr) * NQKV +
                       (kh * 4 + pair * 2 + hp) * 64 + ch;
        __nv_bfloat16* dst = part ? Qlo : Qhi;
        *reinterpret_cast<uint4*>(&dst[m * 72 + ch]) =
            *reinterpret_cast<const uint4*>(&src[gaddr]);
    }
    if (tid < 128) { m_sh[tid] = -1e30f; l_sh[tid] = 0.0f; }

    const int srow = tid >> 1;
    const int sc0 = (tid & 1) * 32;
    const int srr = srow & 63;
    float ov[32];
#pragma unroll
    for (int i = 0; i < 32; i++) ov[i] = 0.0f;

    for (int kt = 0; kt <= qt; kt++) {
        const int s0k = kt * 64;
        cp_wait0();
        __syncthreads();

        {
            wmma::fragment<wmma::accumulator, 16, 16, 16, float> accs[4];
#pragma unroll
            for (int j = 0; j < 4; j++) wmma::fill_fragment(accs[j], 0.0f);
#pragma unroll
            for (int ks = 0; ks < 4; ks++) {
                wmma::fragment<wmma::matrix_a, 16, 16, 16, __nv_bfloat16, wmma::row_major> a_hi, a_lo;
                wmma::load_matrix_sync(a_hi, &Qhi[m0w * 72 + ks * 16], 72);
                wmma::load_matrix_sync(a_lo, &Qlo[m0w * 72 + ks * 16], 72);
#pragma unroll
                for (int j = 0; j < 4; j++) {
                    wmma::fragment<wmma::matrix_b, 16, 16, 16, __nv_bfloat16, wmma::col_major> b_hi, b_lo;
                    wmma::load_matrix_sync(b_hi, &Khi[(j * 16) * 72 + ks * 16], 72);
                    wmma::load_matrix_sync(b_lo, &Klo[(j * 16) * 72 + ks * 16], 72);
                    wmma::mma_sync(accs[j], a_hi, b_hi, accs[j]);
                    wmma::mma_sync(accs[j], a_hi, b_lo, accs[j]);
                    wmma::mma_sync(accs[j], a_lo, b_hi, accs[j]);
                }
            }
#pragma unroll
            for (int j = 0; j < 4; j++)
                wmma::store_matrix_sync(&Sf[m0w * 68 + j * 16], accs[j], 68, wmma::mem_row_major);
        }
        __syncthreads();

        float sv[32];
        {
            float vmax = -1e30f;
#pragma unroll
            for (int i = 0; i < 32; i++) {
                float s = Sf[srow * 68 + sc0 + i] * 0.125f;
                if (s0k + sc0 + i > s0q + srr) s = -1e30f;
                sv[i] = s;
                vmax = fmaxf(vmax, s);
            }
            vmax = fmaxf(vmax, __shfl_xor_sync(0xffffffffu, vmax, 1));
            float mo = m_sh[srow];
            float mx = fmaxf(mo, vmax);
            float al = __expf(mo - mx);
            __syncthreads();
            float sum = 0.0f;
#pragma unroll
            for (int i = 0; i < 32; i++) {
                float p = __expf(sv[i] - mx);
                sum += p;
                __nv_bfloat16 ph = __float2bfloat16(p);
                Phi[srow * 72 + sc0 + i] = ph;
                Plo[srow * 72 + sc0 + i] = __float2bfloat16(p - __bfloat162float(ph));
            }
            sum += __shfl_xor_sync(0xffffffffu, sum, 1);
            if ((tid & 1) == 0) {
                m_sh[srow] = mx;
                l_sh[srow] = l_sh[srow] * al + sum;
                al_sh[srow] = al;
            }
        }
        __syncthreads();

        {
            wmma::fragment<wmma::accumulator, 16, 16, 16, float> acco[4];
#pragma unroll
            for (int j = 0; j < 4; j++) wmma::fill_fragment(acco[j], 0.0f);
#pragma unroll
            for (int ks = 0; ks < 4; ks++) {
                wmma::fragment<wmma::matrix_a, 16, 16, 16, __nv_bfloat16, wmma::row_major> p_hi, p_lo;
                wmma::load_matrix_sync(p_hi, &Phi[m0w * 72 + ks * 16], 72);
                wmma::load_matrix_sync(p_lo, &Plo[m0w * 72 + ks * 16], 72);
#pragma unroll
                for (int j = 0; j < 4; j++) {
                    wmma::fragment<wmma::matrix_b, 16, 16, 16, __nv_bfloat16, wmma::row_major> v_hi, v_lo;
                    wmma::load_matrix_sync(v_hi, &Vhi[(ks * 16) * 72 + j * 16], 72);
                    wmma::load_matrix_sync(v_lo, &Vlo[(ks * 16) * 72 + j * 16], 72);
                    wmma::mma_sync(acco[j], p_hi, v_hi, acco[j]);
                    wmma::mma_sync(acco[j], p_hi, v_lo, acco[j]);
                    wmma::mma_sync(acco[j], p_lo, v_hi, acco[j]);
                }
            }
            __syncthreads();

            if (kt < qt) load_kv(s0k + 64);

#pragma unroll
            for (int j = 0; j < 4; j++)
                wmma::store_matrix_sync(&Sf[m0w * 68 + j * 16], acco[j], 68, wmma::mem_row_major);
        }
        __syncthreads();

        {
            float al = al_sh[srow];
#pragma unroll
            for (int i = 0; i < 32; i++)
                ov[i] = ov[i] * al + Sf[srow * 68 + sc0 + i];
        }
    }

    float invl = 1.0f / l_sh[srow];
    int hp = srow >> 6;
#pragma unroll
    for (int i = 0; i < 32; i++) {
        float f = ov[i] * invl;
        size_t oaddr = (size_t)(b * SS + s0q + srr) * DD +
                       (kh * 4 + pair * 2 + hp) * 64 + sc0 + i;
        __nv_bfloat16 h = __float2bfloat16(f);
        ohi[oaddr] = h;
        olo[oaddr] = __float2bfloat16(f - __bfloat162float(h));
    }
}

// ---------------------------------------------------------------------------
// Launch: preprocessing on origin stream, then batch-pipelined fork/join.
// ---------------------------------------------------------------------------
extern "C" void kernel_launch(void* const* d_in, const int* in_sizes, int n_in,
                              void* d_out, int out_size) {
    const float* x  = (const float*)d_in[0];
    const float* Wq = (const float*)d_in[2];
    const float* bq = (const float*)d_in[3];
    const float* Wk = (const float*)d_in[4];
    const float* bk = (const float*)d_in[5];
    const float* Wv = (const float*)d_in[6];
    const float* bv = (const float*)d_in[7];
    const float* Wo = (const float*)d_in[8];
    const float* bo = (const float*)d_in[9];
    float* out = (float*)d_out;

    float *gc, *gs, *gbqkv;
    cudaGetSymbolAddress((void**)&gc, g_cos);
    cudaGetSymbolAddress((void**)&gs, g_sin);
    cudaGetSymbolAddress((void**)&gbqkv, g_bqkv);

    __nv_bfloat16 *xhi, *xlo, *ohi, *olo, *wqkvhi, *wqkvlo, *wohi, *wolo, *qkvhi, *qkvlo;
    cudaGetSymbolAddress((void**)&xhi, g_xhi);
    cudaGetSymbolAddress((void**)&xlo, g_xlo);
    cudaGetSymbolAddress((void**)&ohi, g_ohi);
    cudaGetSymbolAddress((void**)&olo, g_olo);
    cudaGetSymbolAddress((void**)&wqkvhi, g_wqkvhi);
    cudaGetSymbolAddress((void**)&wqkvlo, g_wqkvlo);
    cudaGetSymbolAddress((void**)&wohi, g_wohi);
    cudaGetSymbolAddress((void**)&wolo, g_wolo);
    cudaGetSymbolAddress((void**)&qkvhi, g_qkvhi);
    cudaGetSymbolAddress((void**)&qkvlo, g_qkvlo);

    // One-time stream/event setup (host resources only; created outside capture
    // on the first correctness call).
    static cudaStream_t s2 = nullptr;
    static cudaEvent_t eFork = nullptr, eJoin = nullptr;
    static bool attr_set = false;
    if (s2 == nullptr) {
        cudaStreamCreateWithFlags(&s2, cudaStreamNonBlocking);
        cudaEventCreateWithFlags(&eFork, cudaEventDisableTiming);
        cudaEventCreateWithFlags(&eJoin, cudaEventDisableTiming);
    }
    if (!attr_set) {
        cudaFuncSetAttribute(gemm_qkv_rope, cudaFuncAttributeMaxDynamicSharedMemorySize,
                             GSM_TOTAL);
        cudaFuncSetAttribute(gemm_out_bias, cudaFuncAttributeMaxDynamicSharedMemorySize,
                             GSM_TOTAL);
        cudaFuncSetAttribute(flash_tc_v3, cudaFuncAttributeMaxDynamicSharedMemorySize,
                             F3_SMEM_TOTAL);
        attr_set = true;
    }

    const int M = BB * SS;   // 4096
    const int MB = SS;       // rows per batch = 2048
    dim3 blk(128);

    // ---- preprocessing on origin stream ----
    rope_table_kernel<<<(SS * 32 + 255) / 256, 256>>>(gc, gs);
    int nx = M * DD;
    split_kernel<<<(nx + 255) / 256, 256>>>(x, xhi, xlo, nx);
    pack_wqkv_kernel<<<(DD * NQKV + 255) / 256, 256>>>(Wq, Wk, Wv, bq, bk, bv,
                                                       wqkvhi, wqkvlo, gbqkv);
    split_kernel<<<(DD * DD + 255) / 256, 256>>>(Wo, wohi, wolo, DD * DD);

    // ---- fork: batch 1 pipeline on s2 ----
    cudaEventRecord(eFork, 0);
    cudaStreamWaitEvent(s2, eFork, 0);

    // batch 0 (origin stream)
    gemm_qkv_rope<<<dim3(NQKV / 128, MB / 128), blk, GSM_TOTAL>>>(
        xhi, xlo, wqkvhi, wqkvlo, gbqkv, gc, gs, qkvhi, qkvlo, M, NQKV, 1024, 0);
    flash_tc_v3<<<dim3(SS / 64, KHH * 2, 1), 256, F3_SMEM_TOTAL>>>(
        qkvhi, qkvlo, ohi, olo, 0);
    gemm_out_bias<<<dim3(1024 / 128, MB / 128), blk, GSM_TOTAL>>>(
        ohi, olo, wohi, wolo, bo, out, M, 1024, 1024, 0);

    // batch 1 (s2)
    gemm_qkv_rope<<<dim3(NQKV / 128, MB / 128), blk, GSM_TOTAL, s2>>>(
        xhi, xlo, wqkvhi, wqkvlo, gbqkv, gc, gs, qkvhi, qkvlo, M, NQKV, 1024, MB);
    flash_tc_v3<<<dim3(SS / 64, KHH * 2, 1), 256, F3_SMEM_TOTAL, s2>>>(
        qkvhi, qkvlo, ohi, olo, 1);
    gemm_out_bias<<<dim3(1024 / 128, MB / 128), blk, GSM_TOTAL, s2>>>(
        ohi, olo, wohi, wolo, bo, out, M, 1024, 1024, MB);

    // ---- join ----
    cudaEventRecord(eJoin, s2);
    cudaStreamWaitEvent(0, eJoin, 0);
}

// round 16
// speedup vs baseline: 1.4873x; 1.4873x over previous
#include <cuda_runtime.h>
#include <cuda_fp16.h>
#include <mma.h>
#include <math.h>
#include <cstdint>

using namespace nvcuda;

#define BB 2
#define SS 2048
#define DD 1024
#define HH 16
#define KHH 4
#define DKK 64
#define REP 4
#define NQKV 1536   // 1024 Q | 256 K | 256 V

// fp32 scratch
__device__ float g_cos[SS * 32];
__device__ float g_sin[SS * 32];
__device__ float g_bqkv[NQKV];

// fp16 scratch: activations split hi/lo, weights single
__device__ __half g_xhi[BB * SS * DD],  g_xlo[BB * SS * DD];
__device__ __half g_ohi[BB * SS * DD],  g_olo[BB * SS * DD];
__device__ __half g_wqkv[DD * NQKV];
__device__ __half g_wo[DD * DD];
__device__ __half g_qkvhi[BB * SS * NQKV], g_qkvlo[BB * SS * NQKV];

// ---------------------------------------------------------------------------
// cp.async helpers
// ---------------------------------------------------------------------------
__device__ __forceinline__ void cp_async16(void* sptr, const void* gptr) {
    unsigned int s = (unsigned int)__cvta_generic_to_shared(sptr);
    asm volatile("cp.async.cg.shared.global [%0], [%1], 16;\n" :: "r"(s), "l"(gptr));
}
__device__ __forceinline__ void cp_commit() { asm volatile("cp.async.commit_group;\n"); }
__device__ __forceinline__ void cp_wait1() { asm volatile("cp.async.wait_group 1;\n"); }
__device__ __forceinline__ void cp_wait0() { asm volatile("cp.async.wait_group 0;\n"); }

// ---------------------------------------------------------------------------
// Small kernels
// ---------------------------------------------------------------------------
__global__ void split_kernel(const float* __restrict__ in,
                             __half* __restrict__ hi,
                             __half* __restrict__ lo, int n) {
    int i = blockIdx.x * blockDim.x + threadIdx.x;
    if (i >= n) return;
    float f = in[i];
    __half h = __float2half_rn(f);
    hi[i] = h;
    lo[i] = __float2half_rn(f - __half2float(h));
}

__global__ void cvt_half_kernel(const float* __restrict__ in,
                                __half* __restrict__ out, int n) {
    int i = blockIdx.x * blockDim.x + threadIdx.x;
    if (i < n) out[i] = __float2half_rn(in[i]);
}

__global__ void pack_wqkv_kernel(const float* __restrict__ Wq, const float* __restrict__ Wk,
                                 const float* __restrict__ Wv, const float* __restrict__ bq,
                                 const float* __restrict__ bk, const float* __restrict__ bv,
                                 __half* __restrict__ w, float* __restrict__ bqkv) {
    int i = blockIdx.x * blockDim.x + threadIdx.x;
    int n = DD * NQKV;
    if (i < NQKV) {
        int c = i;
        bqkv[c] = (c < 1024) ? bq[c] : (c < 1280 ? bk[c - 1024] : bv[c - 1280]);
    }
    if (i >= n) return;
    int row = i / NQKV;
    int col = i % NQKV;
    float f;
    if (col < 1024)      f = Wq[row * 1024 + col];
    else if (col < 1280) f = Wk[row * 256 + col - 1024];
    else                 f = Wv[row * 256 + col - 1280];
    w[i] = __float2half_rn(f);
}

__global__ void rope_table_kernel(float* __restrict__ ctab, float* __restrict__ stab) {
    int idx = blockIdx.x * blockDim.x + threadIdx.x;
    if (idx >= SS * 32) return;
    int s = idx >> 5;
    int d = idx & 31;
    double theta = pow(10000.0, -(double)d / 32.0);
    double f = (double)s * theta;
    ctab[idx] = (float)cos(f);
    stab[idx] = (float)sin(f);
}

// ---------------------------------------------------------------------------
// GEMM v5 (fp16 2-mma): 128x128 block, 128 threads = 4 warps (2m x 2n),
// warp tile 64x64, BK=32 double-buffered cp.async, 2 CTAs/SM.
// A split hi/lo, B single. C = Ahi@B + Alo@B.
// ---------------------------------------------------------------------------
#define GSM_A_BYTES (2 * 2 * 128 * 40 * 2)   // 40960
#define GSM_B_BYTES (2 * 32 * 136 * 2)       // 17408
#define GSM_EPI_BYTES (4 * 64 * 68 * 4)      // 69632 (fp32 staging)
#define GSM_TOTAL 69632                      // max(40960+17408, 69632)

__device__ __forceinline__ int sA_idx(int buf, int part, int r, int c) {
    return ((buf * 2 + part) * 128 + r) * 40 + c;
}
__device__ __forceinline__ int sB_idx(int buf, int r, int c) {
    return (buf * 32 + r) * 136 + c;
}

struct GemmCtx {
    const __half *Ahi, *Alo, *B;
    int M, N, K, m0, n0, tid;
    __half *sA, *sB;
};

__device__ __forceinline__ void gemm_mainloop(
    GemmCtx& g, wmma::fragment<wmma::accumulator, 16, 16, 16, float> (&acc)[4][4],
    int wm, int wn) {
    const int nk = g.K / 32;
    auto load_stage = [&](int buf, int k0) {
#pragma unroll
        for (int t = g.tid; t < 1024; t += 128) {
            int part = t >> 9;
            int c = t & 511;
            int r = c >> 2;
            int cc = (c & 3) * 8;
            size_t gm = (size_t)(g.m0 + r) * g.K + k0 + cc;
            cp_async16(&g.sA[sA_idx(buf, part, r, cc)], part ? &g.Alo[gm] : &g.Ahi[gm]);
        }
#pragma unroll
        for (int t = g.tid; t < 512; t += 128) {
            int r = t >> 4;
            int cc = (t & 15) * 8;
            size_t gm = (size_t)(k0 + r) * g.N + g.n0 + cc;
            cp_async16(&g.sB[sB_idx(buf, r, cc)], &g.B[gm]);
        }
        cp_commit();
    };

    load_stage(0, 0);

    for (int kt = 0; kt < nk; kt++) {
        int buf = kt & 1;
        if (kt + 1 < nk) {
            load_stage(buf ^ 1, (kt + 1) * 32);
            cp_wait1();
        } else {
            cp_wait0();
        }
        __syncthreads();

#pragma unroll
        for (int ks = 0; ks < 2; ks++) {
            wmma::fragment<wmma::matrix_a, 16, 16, 16, __half, wmma::row_major> ahi[4], alo[4];
#pragma unroll
            for (int i = 0; i < 4; i++) {
                wmma::load_matrix_sync(ahi[i], &g.sA[sA_idx(buf, 0, wm * 64 + i * 16, ks * 16)], 40);
                wmma::load_matrix_sync(alo[i], &g.sA[sA_idx(buf, 1, wm * 64 + i * 16, ks * 16)], 40);
            }
#pragma unroll
            for (int j = 0; j < 4; j++) {
                wmma::fragment<wmma::matrix_b, 16, 16, 16, __half, wmma::row_major> bfr;
                wmma::load_matrix_sync(bfr, &g.sB[sB_idx(buf, ks * 16, wn * 64 + j * 16)], 136);
#pragma unroll
                for (int i = 0; i < 4; i++) {
                    wmma::mma_sync(acc[i][j], ahi[i], bfr, acc[i][j]);
                    wmma::mma_sync(acc[i][j], alo[i], bfr, acc[i][j]);
                }
            }
        }
        __syncthreads();
    }
}

// ---------------------------------------------------------------------------
// QKV GEMM + fused bias + RoPE + output-format epilogue.
// Q heads (cols<1024): write fp16 hi/lo. K heads [1024,1280): rope, fp16 single
// (hi only). V heads: bias only, fp16 single.
// ---------------------------------------------------------------------------
__global__ __launch_bounds__(128, 2)
void gemm_qkv_rope(const __half* __restrict__ Ahi,
                   const __half* __restrict__ Alo,
                   const __half* __restrict__ Bw,
                   const float* __restrict__ bias,
                   const float* __restrict__ ctab,
                   const float* __restrict__ stab,
                   __half* __restrict__ ohi,
                   __half* __restrict__ olo,
                   int M, int N, int K, int m_off) {
    extern __shared__ __align__(16) unsigned char smraw[];
    GemmCtx g;
    g.Ahi = Ahi; g.Alo = Alo; g.B = Bw;
    g.M = M; g.N = N; g.K = K;
    g.tid = threadIdx.x;
    g.m0 = m_off + blockIdx.y * 128;
    g.n0 = blockIdx.x * 128;
    g.sA = (__half*)smraw;
    g.sB = (__half*)(smraw + GSM_A_BYTES);

    const int warp = threadIdx.x >> 5;
    const int lane = threadIdx.x & 31;
    const int wm = warp >> 1;
    const int wn = warp & 1;

    wmma::fragment<wmma::accumulator, 16, 16, 16, float> acc[4][4];
#pragma unroll
    for (int i = 0; i < 4; i++)
#pragma unroll
        for (int j = 0; j < 4; j++) wmma::fill_fragment(acc[i][j], 0.0f);

    gemm_mainloop(g, acc, wm, wn);

    float* stg = (float*)(smraw) + warp * (64 * 68);
#pragma unroll
    for (int i = 0; i < 4; i++)
#pragma unroll
        for (int j = 0; j < 4; j++)
            wmma::store_matrix_sync(&stg[(i * 16) * 68 + j * 16], acc[i][j], 68,
                                    wmma::mem_row_major);
    __syncwarp();

    const int col_base = g.n0 + wn * 64;
    const int row_base = g.m0 + wm * 64;

    if (col_base < 1024) {
        // Q head: rope + hi/lo split
        for (int t = lane; t < 2048; t += 32) {
            int r = t >> 5;
            int d = t & 31;
            float x1 = stg[r * 68 + d] + bias[col_base + d];
            float x2 = stg[r * 68 + d + 32] + bias[col_base + d + 32];
            int grow = row_base + r;
            int s = grow & (SS - 1);
            float c = ctab[s * 32 + d];
            float sn = stab[s * 32 + d];
            float r1 = x1 * c - x2 * sn;
            float r2 = x2 * c + x1 * sn;
            size_t base = (size_t)grow * NQKV + col_base + d;
            __half h1 = __float2half_rn(r1);
            __half h2 = __float2half_rn(r2);
            ohi[base] = h1;
            olo[base] = __float2half_rn(r1 - __half2float(h1));
            ohi[base + 32] = h2;
            olo[base + 32] = __float2half_rn(r2 - __half2float(h2));
        }
    } else if (col_base < 1280) {
        // K head: rope + single fp16
        for (int t = lane; t < 2048; t += 32) {
            int r = t >> 5;
            int d = t & 31;
            float x1 = stg[r * 68 + d] + bias[col_base + d];
            float x2 = stg[r * 68 + d + 32] + bias[col_base + d + 32];
            int grow = row_base + r;
            int s = grow & (SS - 1);
            float c = ctab[s * 32 + d];
            float sn = stab[s * 32 + d];
            size_t base = (size_t)grow * NQKV + col_base + d;
            ohi[base] = __float2half_rn(x1 * c - x2 * sn);
            ohi[base + 32] = __float2half_rn(x2 * c + x1 * sn);
        }
    } else {
        // V head: bias + single fp16
        for (int t = lane; t < 4096; t += 32) {
            int r = t >> 6;
            int d = t & 63;
            float f = stg[r * 68 + d] + bias[col_base + d];
            ohi[(size_t)(row_base + r) * NQKV + col_base + d] = __float2half_rn(f);
        }
    }
}

// ---------------------------------------------------------------------------
// Output-projection GEMM with fused bias (fp32 out).
// ---------------------------------------------------------------------------
__global__ __launch_bounds__(128, 2)
void gemm_out_bias(const __half* __restrict__ Ahi,
                   const __half* __restrict__ Alo,
                   const __half* __restrict__ Bw,
                   const float* __restrict__ bias,
                   float* __restrict__ C, int M, int N, int K, int m_off) {
    extern __shared__ __align__(16) unsigned char smraw[];
    GemmCtx g;
    g.Ahi = Ahi; g.Alo = Alo; g.B = Bw;
    g.M = M; g.N = N; g.K = K;
    g.tid = threadIdx.x;
    g.m0 = m_off + blockIdx.y * 128;
    g.n0 = blockIdx.x * 128;
    g.sA = (__half*)smraw;
    g.sB = (__half*)(smraw + GSM_A_BYTES);

    const int warp = threadIdx.x >> 5;
    const int lane = threadIdx.x & 31;
    const int wm = warp >> 1;
    const int wn = warp & 1;

    wmma::fragment<wmma::accumulator, 16, 16, 16, float> acc[4][4];
#pragma unroll
    for (int i = 0; i < 4; i++)
#pragma unroll
        for (int j = 0; j < 4; j++) wmma::fill_fragment(acc[i][j], 0.0f);

    gemm_mainloop(g, acc, wm, wn);

    float* stg = (float*)(smraw) + warp * (64 * 68);
#pragma unroll
    for (int i = 0; i < 4; i++)
#pragma unroll
        for (int j = 0; j < 4; j++)
            wmma::store_matrix_sync(&stg[(i * 16) * 68 + j * 16], acc[i][j], 68,
                                    wmma::mem_row_major);
    __syncwarp();

    const int col_base = g.n0 + wn * 64;
    const int row_base = g.m0 + wm * 64;
    for (int t = lane; t < 4096; t += 32) {
        int r = t >> 6;
        int d = t & 63;
        C[(size_t)(row_base + r) * g.N + col_base + d] =
            stg[r * 68 + d] + bias[col_base + d];
    }
}

// ---------------------------------------------------------------------------
// flash_tc_v4 (fp16 2-mma): M=128 (2 Q-heads), 256 threads/8 warps, 2 CTAs/SM.
// Q hi/lo fp16; K, V single fp16; P hi/lo fp16.
// ---------------------------------------------------------------------------
#define F4_QHI 0
#define F4_QLO 18432
#define F4_K   36864
#define F4_V   46080
#define F4_SFP 55296            // Sf f32 (128x68 = 34816) / P hi|lo (2x18432) union
#define F4_PHI 55296
#define F4_PLO 73728
#define F4_M   92160
#define F4_L   92672
#define F4_AL  93184
#define F4_SMEM_TOTAL 93696

__global__ __launch_bounds__(256, 2)
void flash_tc_v4(const __half* __restrict__ qh,
                 const __half* __restrict__ ql,
                 __half* __restrict__ ohi,
                 __half* __restrict__ olo, int b) {
    extern __shared__ __align__(16) unsigned char fsm[];
    __half* Qhi = (__half*)(fsm + F4_QHI);
    __half* Qlo = (__half*)(fsm + F4_QLO);
    __half* Ks  = (__half*)(fsm + F4_K);
    __half* Vs  = (__half*)(fsm + F4_V);
    float* Sf   = (float*)(fsm + F4_SFP);
    __half* Phi = (__half*)(fsm + F4_PHI);
    __half* Plo = (__half*)(fsm + F4_PLO);
    float* m_sh = (float*)(fsm + F4_M);
    float* l_sh = (float*)(fsm + F4_L);
    float* al_sh= (float*)(fsm + F4_AL);

    const int tid = threadIdx.x;
    const int warp = tid >> 5;
    const int qt = (int)gridDim.x - 1 - (int)blockIdx.x;   // long blocks first
    const int kh = blockIdx.y >> 1;
    const int pair = blockIdx.y & 1;
    const int s0q = qt * 64;
    const int m0w = warp * 16;

    // K and V tiles: single fp16, 64 rows x 64 cols each
    auto load_kv = [&](int s0k) {
        for (int t = tid; t < 1024; t += 256) {
            int arr = t >> 9;               // 0:K 1:V
            int r = (t >> 3) & 63;
            int ch = (t & 7) * 8;
            size_t g = (size_t)(b * SS + s0k + r) * NQKV + 1024 + kh * 64 +
                       (arr ? 256 : 0) + ch;
            cp_async16(arr ? &Vs[r * 72 + ch] : &Ks[r * 72 + ch], &qh[g]);
        }
        cp_commit();
    };

    load_kv(0);

    // Q for 2 heads (hi/lo)
    for (int t = tid; t < 2048; t += 256) {
        int part = t >> 10;
        int m = (t >> 3) & 127;
        int ch = (t & 7) * 8;
        int hp = m >> 6;
        int rr = m & 63;
        const __half* src = part ? ql : qh;
        size_t gaddr = (size_t)(b * SS + s0q + rr) * NQKV +
                       (kh * 4 + pair * 2 + hp) * 64 + ch;
        __half* dst = part ? Qlo : Qhi;
        *reinterpret_cast<uint4*>(&dst[m * 72 + ch]) =
            *reinterpret_cast<const uint4*>(&src[gaddr]);
    }
    if (tid < 128) { m_sh[tid] = -1e30f; l_sh[tid] = 0.0f; }

    const int srow = tid >> 1;
    const int sc0 = (tid & 1) * 32;
    const int srr = srow & 63;
    float ov[32];
#pragma unroll
    for (int i = 0; i < 32; i++) ov[i] = 0.0f;

    for (int kt = 0; kt <= qt; kt++) {
        const int s0k = kt * 64;
        cp_wait0();
        __syncthreads();

        // S = Q @ K^T (2-mma)
        {
            wmma::fragment<wmma::accumulator, 16, 16, 16, float> accs[4];
#pragma unroll
            for (int j = 0; j < 4; j++) wmma::fill_fragment(accs[j], 0.0f);
#pragma unroll
            for (int ks = 0; ks < 4; ks++) {
                wmma::fragment<wmma::matrix_a, 16, 16, 16, __half, wmma::row_major> a_hi, a_lo;
                wmma::load_matrix_sync(a_hi, &Qhi[m0w * 72 + ks * 16], 72);
                wmma::load_matrix_sync(a_lo, &Qlo[m0w * 72 + ks * 16], 72);
#pragma unroll
                for (int j = 0; j < 4; j++) {
                    wmma::fragment<wmma::matrix_b, 16, 16, 16, __half, wmma::col_major> b_k;
                    wmma::load_matrix_sync(b_k, &Ks[(j * 16) * 72 + ks * 16], 72);
                    wmma::mma_sync(accs[j], a_hi, b_k, accs[j]);
                    wmma::mma_sync(accs[j], a_lo, b_k, accs[j]);
                }
            }
#pragma unroll
            for (int j = 0; j < 4; j++)
                wmma::store_matrix_sync(&Sf[m0w * 68 + j * 16], accs[j], 68, wmma::mem_row_major);
        }
        __syncthreads();

        // softmax (2 threads/row), register-staged (Sf/P alias)
        float sv[32];
        {
            float vmax = -1e30f;
#pragma unroll
            for (int i = 0; i < 32; i++) {
                float s = Sf[srow * 68 + sc0 + i] * 0.125f;
                if (s0k + sc0 + i > s0q + srr) s = -1e30f;
                sv[i] = s;
                vmax = fmaxf(vmax, s);
            }
            vmax = fmaxf(vmax, __shfl_xor_sync(0xffffffffu, vmax, 1));
            float mo = m_sh[srow];
            float mx = fmaxf(mo, vmax);
            float al = __expf(mo - mx);
            __syncthreads();
            float sum = 0.0f;
#pragma unroll
            for (int i = 0; i < 32; i++) {
                float p = __expf(sv[i] - mx);
                sum += p;
                __half ph = __float2half_rn(p);
                Phi[srow * 72 + sc0 + i] = ph;
                Plo[srow * 72 + sc0 + i] = __float2half_rn(p - __half2float(ph));
            }
            sum += __shfl_xor_sync(0xffffffffu, sum, 1);
            if ((tid & 1) == 0) {
                m_sh[srow] = mx;
                l_sh[srow] = l_sh[srow] * al + sum;
                al_sh[srow] = al;
            }
        }
        __syncthreads();

        // PV (2-mma)
        {
            wmma::fragment<wmma::accumulator, 16, 16, 16, float> acco[4];
#pragma unroll
            for (int j = 0; j < 4; j++) wmma::fill_fragment(acco[j], 0.0f);
#pragma unroll
            for (int ks = 0; ks < 4; ks++) {
                wmma::fragment<wmma::matrix_a, 16, 16, 16, __half, wmma::row_major> p_hi, p_lo;
                wmma::load_matrix_sync(p_hi, &Phi[m0w * 72 + ks * 16], 72);
                wmma::load_matrix_sync(p_lo, &Plo[m0w * 72 + ks * 16], 72);
#pragma unroll
                for (int j = 0; j < 4; j++) {
                    wmma::fragment<wmma::matrix_b, 16, 16, 16, __half, wmma::row_major> v_f;
                    wmma::load_matrix_sync(v_f, &Vs[(ks * 16) * 72 + j * 16], 72);
                    wmma::mma_sync(acco[j], p_hi, v_f, acco[j]);
                    wmma::mma_sync(acco[j], p_lo, v_f, acco[j]);
                }
            }
            __syncthreads();

            if (kt < qt) load_kv(s0k + 64);

#pragma unroll
            for (int j = 0; j < 4; j++)
                wmma::store_matrix_sync(&Sf[m0w * 68 + j * 16], acco[j], 68, wmma::mem_row_major);
        }
        __syncthreads();

        {
            float al = al_sh[srow];
#pragma unroll
            for (int i = 0; i < 32; i++)
                ov[i] = ov[i] * al + Sf[srow * 68 + sc0 + i];
        }
    }

    float invl = 1.0f / l_sh[srow];
    int hp = srow >> 6;
#pragma unroll
    for (int i = 0; i < 32; i++) {
        float f = ov[i] * invl;
        size_t oaddr = (size_t)(b * SS + s0q + srr) * DD +
                       (kh * 4 + pair * 2 + hp) * 64 + sc0 + i;
        __half h = __float2half_rn(f);
        ohi[oaddr] = h;
        olo[oaddr] = __float2half_rn(f - __half2float(h));
    }
}

// ---------------------------------------------------------------------------
// Launch: preprocessing on origin stream, then batch-pipelined fork/join.
// ---------------------------------------------------------------------------
extern "C" void kernel_launch(void* const* d_in, const int* in_sizes, int n_in,
                              void* d_out, int out_size) {
    const float* x  = (const float*)d_in[0];
    const float* Wq = (const float*)d_in[2];
    const float* bq = (const float*)d_in[3];
    const float* Wk = (const float*)d_in[4];
    const float* bk = (const float*)d_in[5];
    const float* Wv = (const float*)d_in[6];
    const float* bv = (const float*)d_in[7];
    const float* Wo = (const float*)d_in[8];
    const float* bo = (const float*)d_in[9];
    float* out = (float*)d_out;

    float *gc, *gs, *gbqkv;
    cudaGetSymbolAddress((void**)&gc, g_cos);
    cudaGetSymbolAddress((void**)&gs, g_sin);
    cudaGetSymbolAddress((void**)&gbqkv, g_bqkv);

    __half *xhi, *xlo, *ohi, *olo, *wqkv, *wo, *qkvhi, *qkvlo;
    cudaGetSymbolAddress((void**)&xhi, g_xhi);
    cudaGetSymbolAddress((void**)&xlo, g_xlo);
    cudaGetSymbolAddress((void**)&ohi, g_ohi);
    cudaGetSymbolAddress((void**)&olo, g_olo);
    cudaGetSymbolAddress((void**)&wqkv, g_wqkv);
    cudaGetSymbolAddress((void**)&wo, g_wo);
    cudaGetSymbolAddress((void**)&qkvhi, g_qkvhi);
    cudaGetSymbolAddress((void**)&qkvlo, g_qkvlo);

    static cudaStream_t s2 = nullptr;
    static cudaEvent_t eFork = nullptr, eJoin = nullptr;
    static bool attr_set = false;
    if (s2 == nullptr) {
        cudaStreamCreateWithFlags(&s2, cudaStreamNonBlocking);
        cudaEventCreateWithFlags(&eFork, cudaEventDisableTiming);
        cudaEventCreateWithFlags(&eJoin, cudaEventDisableTiming);
    }
    if (!attr_set) {
        cudaFuncSetAttribute(gemm_qkv_rope, cudaFuncAttributeMaxDynamicSharedMemorySize,
                             GSM_TOTAL);
        cudaFuncSetAttribute(gemm_out_bias, cudaFuncAttributeMaxDynamicSharedMemorySize,
                             GSM_TOTAL);
        cudaFuncSetAttribute(flash_tc_v4, cudaFuncAttributeMaxDynamicSharedMemorySize,
                             F4_SMEM_TOTAL);
        attr_set = true;
    }

    const int M = BB * SS;   // 4096
    const int MB = SS;       // rows per batch
    dim3 blk(128);

    // ---- preprocessing on origin stream ----
    rope_table_kernel<<<(SS * 32 + 255) / 256, 256>>>(gc, gs);
    int nx = M * DD;
    split_kernel<<<(nx + 255) / 256, 256>>>(x, xhi, xlo, nx);
    pack_wqkv_kernel<<<(DD * NQKV + 255) / 256, 256>>>(Wq, Wk, Wv, bq, bk, bv,
                                                       wqkv, gbqkv);
    cvt_half_kernel<<<(DD * DD + 255) / 256, 256>>>(Wo, wo, DD * DD);

    // ---- fork: batch 1 pipeline on s2 ----
    cudaEventRecord(eFork, 0);
    cudaStreamWaitEvent(s2, eFork, 0);

    // batch 0 (origin stream)
    gemm_qkv_rope<<<dim3(NQKV / 128, MB / 128), blk, GSM_TOTAL>>>(
        xhi, xlo, wqkv, gbqkv, gc, gs, qkvhi, qkvlo, M, NQKV, 1024, 0);
    flash_tc_v4<<<dim3(SS / 64, KHH * 2, 1), 256, F4_SMEM_TOTAL>>>(
        qkvhi, qkvlo, ohi, olo, 0);
    gemm_out_bias<<<dim3(1024 / 128, MB / 128), blk, GSM_TOTAL>>>(
        ohi, olo, wo, bo, out, M, 1024, 1024, 0);

    // batch 1 (s2)
    gemm_qkv_rope<<<dim3(NQKV / 128, MB / 128), blk, GSM_TOTAL, s2>>>(
        xhi, xlo, wqkv, gbqkv, gc, gs, qkvhi, qkvlo, M, NQKV, 1024, MB);
    flash_tc_v4<<<dim3(SS / 64, KHH * 2, 1), 256, F4_SMEM_TOTAL, s2>>>(
        qkvhi, qkvlo, ohi, olo, 1);
    gemm_out_bias<<<dim3(1024 / 128, MB / 128), blk, GSM_TOTAL, s2>>>(
        ohi, olo, wo, bo, out, M, 1024, 1024, MB);

    // ---- join ----
    cudaEventRecord(eJoin, s2);
    cudaStreamWaitEvent(0, eJoin, 0);
}

// round 17
// speedup vs baseline: 2.1146x; 1.4218x over previous
#include <cuda_runtime.h>
#include <cuda_fp16.h>
#include <mma.h>
#include <math.h>
#include <cstdint>

using namespace nvcuda;

#define BB 2
#define SS 2048
#define DD 1024
#define HH 16
#define KHH 4
#define DKK 64
#define REP 4
#define NQKV 1536   // 1024 Q | 256 K | 256 V

// fp32 scratch
__device__ float g_cos[SS * 32];
__device__ float g_sin[SS * 32];
__device__ float g_bqkv[NQKV];

// fp16 scratch (all single precision; fp32 accumulate in mma)
__device__ __half g_x16[BB * SS * DD];
__device__ __half g_o16[BB * SS * DD];
__device__ __half g_wqkv[DD * NQKV];
__device__ __half g_wo[DD * DD];
__device__ __half g_qkv16[BB * SS * NQKV];

// ---------------------------------------------------------------------------
// cp.async helpers
// ---------------------------------------------------------------------------
__device__ __forceinline__ void cp_async16(void* sptr, const void* gptr) {
    unsigned int s = (unsigned int)__cvta_generic_to_shared(sptr);
    asm volatile("cp.async.cg.shared.global [%0], [%1], 16;\n" :: "r"(s), "l"(gptr));
}
__device__ __forceinline__ void cp_commit() { asm volatile("cp.async.commit_group;\n"); }
__device__ __forceinline__ void cp_wait1() { asm volatile("cp.async.wait_group 1;\n"); }
__device__ __forceinline__ void cp_wait0() { asm volatile("cp.async.wait_group 0;\n"); }

// ---------------------------------------------------------------------------
// Small kernels
// ---------------------------------------------------------------------------
__global__ void cvt_half_kernel(const float* __restrict__ in,
                                __half* __restrict__ out, int n) {
    int i = blockIdx.x * blockDim.x + threadIdx.x;
    if (i < n) out[i] = __float2half_rn(in[i]);
}

__global__ void pack_wqkv_kernel(const float* __restrict__ Wq, const float* __restrict__ Wk,
                                 const float* __restrict__ Wv, const float* __restrict__ bq,
                                 const float* __restrict__ bk, const float* __restrict__ bv,
                                 __half* __restrict__ w, float* __restrict__ bqkv) {
    int i = blockIdx.x * blockDim.x + threadIdx.x;
    int n = DD * NQKV;
    if (i < NQKV) {
        int c = i;
        bqkv[c] = (c < 1024) ? bq[c] : (c < 1280 ? bk[c - 1024] : bv[c - 1280]);
    }
    if (i >= n) return;
    int row = i / NQKV;
    int col = i % NQKV;
    float f;
    if (col < 1024)      f = Wq[row * 1024 + col];
    else if (col < 1280) f = Wk[row * 256 + col - 1024];
    else                 f = Wv[row * 256 + col - 1280];
    w[i] = __float2half_rn(f);
}

__global__ void rope_table_kernel(float* __restrict__ ctab, float* __restrict__ stab) {
    int idx = blockIdx.x * blockDim.x + threadIdx.x;
    if (idx >= SS * 32) return;
    int s = idx >> 5;
    int d = idx & 31;
    double theta = pow(10000.0, -(double)d / 32.0);
    double f = (double)s * theta;
    ctab[idx] = (float)cos(f);
    stab[idx] = (float)sin(f);
}

// ---------------------------------------------------------------------------
// GEMM v6 (fp16 single, 1-mma): 128x128 block, 128 threads = 4 warps (2m x 2n),
// warp tile 64x64, BK=32 double-buffered cp.async, 2 CTAs/SM.
// ---------------------------------------------------------------------------
#define GSM_A_BYTES (2 * 128 * 40 * 2)       // 20480
#define GSM_B_BYTES (2 * 32 * 136 * 2)       // 17408
#define GSM_EPI_BYTES (4 * 64 * 68 * 4)      // 69632 (fp32 staging)
#define GSM_TOTAL 69632                      // max(20480+17408, 69632)

__device__ __forceinline__ int sA_idx(int buf, int r, int c) {
    return (buf * 128 + r) * 40 + c;
}
__device__ __forceinline__ int sB_idx(int buf, int r, int c) {
    return (buf * 32 + r) * 136 + c;
}

struct GemmCtx {
    const __half *A, *B;
    int M, N, K, m0, n0, tid;
    __half *sA, *sB;
};

__device__ __forceinline__ void gemm_mainloop(
    GemmCtx& g, wmma::fragment<wmma::accumulator, 16, 16, 16, float> (&acc)[4][4],
    int wm, int wn) {
    const int nk = g.K / 32;
    auto load_stage = [&](int buf, int k0) {
#pragma unroll
        for (int t = g.tid; t < 512; t += 128) {
            int r = t >> 2;
            int cc = (t & 3) * 8;
            size_t gm = (size_t)(g.m0 + r) * g.K + k0 + cc;
            cp_async16(&g.sA[sA_idx(buf, r, cc)], &g.A[gm]);
        }
#pragma unroll
        for (int t = g.tid; t < 512; t += 128) {
            int r = t >> 4;
            int cc = (t & 15) * 8;
            size_t gm = (size_t)(k0 + r) * g.N + g.n0 + cc;
            cp_async16(&g.sB[sB_idx(buf, r, cc)], &g.B[gm]);
        }
        cp_commit();
    };

    load_stage(0, 0);

    for (int kt = 0; kt < nk; kt++) {
        int buf = kt & 1;
        if (kt + 1 < nk) {
            load_stage(buf ^ 1, (kt + 1) * 32);
            cp_wait1();
        } else {
            cp_wait0();
        }
        __syncthreads();

#pragma unroll
        for (int ks = 0; ks < 2; ks++) {
            wmma::fragment<wmma::matrix_a, 16, 16, 16, __half, wmma::row_major> afr[4];
#pragma unroll
            for (int i = 0; i < 4; i++)
                wmma::load_matrix_sync(afr[i], &g.sA[sA_idx(buf, wm * 64 + i * 16, ks * 16)], 40);
#pragma unroll
            for (int j = 0; j < 4; j++) {
                wmma::fragment<wmma::matrix_b, 16, 16, 16, __half, wmma::row_major> bfr;
                wmma::load_matrix_sync(bfr, &g.sB[sB_idx(buf, ks * 16, wn * 64 + j * 16)], 136);
#pragma unroll
                for (int i = 0; i < 4; i++)
                    wmma::mma_sync(acc[i][j], afr[i], bfr, acc[i][j]);
            }
        }
        __syncthreads();
    }
}

// ---------------------------------------------------------------------------
// QKV GEMM + fused bias + RoPE epilogue -> single fp16 qkv buffer.
// ---------------------------------------------------------------------------
__global__ __launch_bounds__(128, 2)
void gemm_qkv_rope(const __half* __restrict__ A,
                   const __half* __restrict__ Bw,
                   const float* __restrict__ bias,
                   const float* __restrict__ ctab,
                   const float* __restrict__ stab,
                   __half* __restrict__ oq,
                   int M, int N, int K, int m_off) {
    extern __shared__ __align__(16) unsigned char smraw[];
    GemmCtx g;
    g.A = A; g.B = Bw;
    g.M = M; g.N = N; g.K = K;
    g.tid = threadIdx.x;
    g.m0 = m_off + blockIdx.y * 128;
    g.n0 = blockIdx.x * 128;
    g.sA = (__half*)smraw;
    g.sB = (__half*)(smraw + GSM_A_BYTES);

    const int warp = threadIdx.x >> 5;
    const int lane = threadIdx.x & 31;
    const int wm = warp >> 1;
    const int wn = warp & 1;

    wmma::fragment<wmma::accumulator, 16, 16, 16, float> acc[4][4];
#pragma unroll
    for (int i = 0; i < 4; i++)
#pragma unroll
        for (int j = 0; j < 4; j++) wmma::fill_fragment(acc[i][j], 0.0f);

    gemm_mainloop(g, acc, wm, wn);

    float* stg = (float*)(smraw) + warp * (64 * 68);
#pragma unroll
    for (int i = 0; i < 4; i++)
#pragma unroll
        for (int j = 0; j < 4; j++)
            wmma::store_matrix_sync(&stg[(i * 16) * 68 + j * 16], acc[i][j], 68,
                                    wmma::mem_row_major);
    __syncwarp();

    const int col_base = g.n0 + wn * 64;
    const int row_base = g.m0 + wm * 64;

    if (col_base < 1280) {
        // Q or K head: bias + rope
        for (int t = lane; t < 2048; t += 32) {
            int r = t >> 5;
            int d = t & 31;
            float x1 = stg[r * 68 + d] + bias[col_base + d];
            float x2 = stg[r * 68 + d + 32] + bias[col_base + d + 32];
            int grow = row_base + r;
            int s = grow & (SS - 1);
            float c = ctab[s * 32 + d];
            float sn = stab[s * 32 + d];
            size_t base = (size_t)grow * NQKV + col_base + d;
            oq[base] = __float2half_rn(x1 * c - x2 * sn);
            oq[base + 32] = __float2half_rn(x2 * c + x1 * sn);
        }
    } else {
        // V head: bias only
        for (int t = lane; t < 4096; t += 32) {
            int r = t >> 6;
            int d = t & 63;
            float f = stg[r * 68 + d] + bias[col_base + d];
            oq[(size_t)(row_base + r) * NQKV + col_base + d] = __float2half_rn(f);
        }
    }
}

// ---------------------------------------------------------------------------
// Output-projection GEMM with fused bias (fp32 out).
// ---------------------------------------------------------------------------
__global__ __launch_bounds__(128, 2)
void gemm_out_bias(const __half* __restrict__ A,
                   const __half* __restrict__ Bw,
                   const float* __restrict__ bias,
                   float* __restrict__ C, int M, int N, int K, int m_off) {
    extern __shared__ __align__(16) unsigned char smraw[];
    GemmCtx g;
    g.A = A; g.B = Bw;
    g.M = M; g.N = N; g.K = K;
    g.tid = threadIdx.x;
    g.m0 = m_off + blockIdx.y * 128;
    g.n0 = blockIdx.x * 128;
    g.sA = (__half*)smraw;
    g.sB = (__half*)(smraw + GSM_A_BYTES);

    const int warp = threadIdx.x >> 5;
    const int lane = threadIdx.x & 31;
    const int wm = warp >> 1;
    const int wn = warp & 1;

    wmma::fragment<wmma::accumulator, 16, 16, 16, float> acc[4][4];
#pragma unroll
    for (int i = 0; i < 4; i++)
#pragma unroll
        for (int j = 0; j < 4; j++) wmma::fill_fragment(acc[i][j], 0.0f);

    gemm_mainloop(g, acc, wm, wn);

    float* stg = (float*)(smraw) + warp * (64 * 68);
#pragma unroll
    for (int i = 0; i < 4; i++)
#pragma unroll
        for (int j = 0; j < 4; j++)
            wmma::store_matrix_sync(&stg[(i * 16) * 68 + j * 16], acc[i][j], 68,
                                    wmma::mem_row_major);
    __syncwarp();

    const int col_base = g.n0 + wn * 64;
    const int row_base = g.m0 + wm * 64;
    for (int t = lane; t < 4096; t += 32) {
        int r = t >> 6;
        int d = t & 63;
        C[(size_t)(row_base + r) * g.N + col_base + d] =
            stg[r * 68 + d] + bias[col_base + d];
    }
}

// ---------------------------------------------------------------------------
// flash_tc_v5 (fp16 single, 1-mma): M=128 (2 Q-heads), 256 thr/8 warps,
// 2 CTAs/SM. smem ~73 KB.
// ---------------------------------------------------------------------------
#define F5_Q   0
#define F5_K   18432
#define F5_V   27648
#define F5_SFP 36864            // Sf f32 (128x68=34816) / P fp16 (18432) union
#define F5_P   36864
#define F5_M   71680
#define F5_L   72192
#define F5_AL  72704
#define F5_SMEM_TOTAL 73216

__global__ __launch_bounds__(256, 2)
void flash_tc_v5(const __half* __restrict__ qkv,
                 __half* __restrict__ og, int b) {
    extern __shared__ __align__(16) unsigned char fsm[];
    __half* Qs = (__half*)(fsm + F5_Q);
    __half* Ks = (__half*)(fsm + F5_K);
    __half* Vs = (__half*)(fsm + F5_V);
    float* Sf  = (float*)(fsm + F5_SFP);
    __half* Ps = (__half*)(fsm + F5_P);
    float* m_sh = (float*)(fsm + F5_M);
    float* l_sh = (float*)(fsm + F5_L);
    float* al_sh= (float*)(fsm + F5_AL);

    const int tid = threadIdx.x;
    const int warp = tid >> 5;
    const int qt = (int)gridDim.x - 1 - (int)blockIdx.x;   // long blocks first
    const int kh = blockIdx.y >> 1;
    const int pair = blockIdx.y & 1;
    const int s0q = qt * 64;
    const int m0w = warp * 16;

    auto load_kv = [&](int s0k) {
        for (int t = tid; t < 1024; t += 256) {
            int arr = t >> 9;               // 0:K 1:V
            int r = (t >> 3) & 63;
            int ch = (t & 7) * 8;
            size_t g = (size_t)(b * SS + s0k + r) * NQKV + 1024 + kh * 64 +
                       (arr ? 256 : 0) + ch;
            cp_async16(arr ? &Vs[r * 72 + ch] : &Ks[r * 72 + ch], &qkv[g]);
        }
        cp_commit();
    };

    load_kv(0);

    // Q for 2 heads (single fp16)
    for (int t = tid; t < 1024; t += 256) {
        int m = t >> 3;
        int ch = (t & 7) * 8;
        int hp = m >> 6;
        int rr = m & 63;
        size_t gaddr = (size_t)(b * SS + s0q + rr) * NQKV +
                       (kh * 4 + pair * 2 + hp) * 64 + ch;
        *reinterpret_cast<uint4*>(&Qs[m * 72 + ch]) =
            *reinterpret_cast<const uint4*>(&qkv[gaddr]);
    }
    if (tid < 128) { m_sh[tid] = -1e30f; l_sh[tid] = 0.0f; }

    const int srow = tid >> 1;
    const int sc0 = (tid & 1) * 32;
    const int srr = srow & 63;
    float ov[32];
#pragma unroll
    for (int i = 0; i < 32; i++) ov[i] = 0.0f;

    for (int kt = 0; kt <= qt; kt++) {
        const int s0k = kt * 64;
        cp_wait0();
        __syncthreads();

        // S = Q @ K^T (1-mma)
        {
            wmma::fragment<wmma::accumulator, 16, 16, 16, float> accs[4];
#pragma unroll
            for (int j = 0; j < 4; j++) wmma::fill_fragment(accs[j], 0.0f);
#pragma unroll
            for (int ks = 0; ks < 4; ks++) {
                wmma::fragment<wmma::matrix_a, 16, 16, 16, __half, wmma::row_major> a_q;
                wmma::load_matrix_sync(a_q, &Qs[m0w * 72 + ks * 16], 72);
#pragma unroll
                for (int j = 0; j < 4; j++) {
                    wmma::fragment<wmma::matrix_b, 16, 16, 16, __half, wmma::col_major> b_k;
                    wmma::load_matrix_sync(b_k, &Ks[(j * 16) * 72 + ks * 16], 72);
                    wmma::mma_sync(accs[j], a_q, b_k, accs[j]);
                }
            }
#pragma unroll
            for (int j = 0; j < 4; j++)
                wmma::store_matrix_sync(&Sf[m0w * 68 + j * 16], accs[j], 68, wmma::mem_row_major);
        }
        __syncthreads();

        // softmax (2 threads/row), register-staged (Sf/P alias)
        float sv[32];
        {
            float vmax = -1e30f;
#pragma unroll
            for (int i = 0; i < 32; i++) {
                float s = Sf[srow * 68 + sc0 + i] * 0.125f;
                if (s0k + sc0 + i > s0q + srr) s = -1e30f;
                sv[i] = s;
                vmax = fmaxf(vmax, s);
            }
            vmax = fmaxf(vmax, __shfl_xor_sync(0xffffffffu, vmax, 1));
            float mo = m_sh[srow];
            float mx = fmaxf(mo, vmax);
            float al = __expf(mo - mx);
            __syncthreads();
            float sum = 0.0f;
#pragma unroll
            for (int i = 0; i < 32; i++) {
                float p = __expf(sv[i] - mx);
                sum += p;
                Ps[srow * 72 + sc0 + i] = __float2half_rn(p);
            }
            sum += __shfl_xor_sync(0xffffffffu, sum, 1);
            if ((tid & 1) == 0) {
                m_sh[srow] = mx;
                l_sh[srow] = l_sh[srow] * al + sum;
                al_sh[srow] = al;
            }
        }
        __syncthreads();

        // PV (1-mma)
        {
            wmma::fragment<wmma::accumulator, 16, 16, 16, float> acco[4];
#pragma unroll
            for (int j = 0; j < 4; j++) wmma::fill_fragment(acco[j], 0.0f);
#pragma unroll
            for (int ks = 0; ks < 4; ks++) {
                wmma::fragment<wmma::matrix_a, 16, 16, 16, __half, wmma::row_major> p_f;
                wmma::load_matrix_sync(p_f, &Ps[m0w * 72 + ks * 16], 72);
#pragma unroll
                for (int j = 0; j < 4; j++) {
                    wmma::fragment<wmma::matrix_b, 16, 16, 16, __half, wmma::row_major> v_f;
                    wmma::load_matrix_sync(v_f, &Vs[(ks * 16) * 72 + j * 16], 72);
                    wmma::mma_sync(acco[j], p_f, v_f, acco[j]);
                }
            }
            __syncthreads();

            if (kt < qt) load_kv(s0k + 64);

#pragma unroll
            for (int j = 0; j < 4; j++)
                wmma::store_matrix_sync(&Sf[m0w * 68 + j * 16], acco[j], 68, wmma::mem_row_major);
        }
        __syncthreads();

        {
            float al = al_sh[srow];
#pragma unroll
            for (int i = 0; i < 32; i++)
                ov[i] = ov[i] * al + Sf[srow * 68 + sc0 + i];
        }
    }

    float invl = 1.0f / l_sh[srow];
    int hp = srow >> 6;
#pragma unroll
    for (int i = 0; i < 32; i++) {
        float f = ov[i] * invl;
        size_t oaddr = (size_t)(b * SS + s0q + srr) * DD +
                       (kh * 4 + pair * 2 + hp) * 64 + sc0 + i;
        og[oaddr] = __float2half_rn(f);
    }
}

// ---------------------------------------------------------------------------
// Launch: preprocessing on origin stream, then batch-pipelined fork/join.
// ---------------------------------------------------------------------------
extern "C" void kernel_launch(void* const* d_in, const int* in_sizes, int n_in,
                              void* d_out, int out_size) {
    const float* x  = (const float*)d_in[0];
    const float* Wq = (const float*)d_in[2];
    const float* bq = (const float*)d_in[3];
    const float* Wk = (const float*)d_in[4];
    const float* bk = (const float*)d_in[5];
    const float* Wv = (const float*)d_in[6];
    const float* bv = (const float*)d_in[7];
    const float* Wo = (const float*)d_in[8];
    const float* bo = (const float*)d_in[9];
    float* out = (float*)d_out;

    float *gc, *gs, *gbqkv;
    cudaGetSymbolAddress((void**)&gc, g_cos);
    cudaGetSymbolAddress((void**)&gs, g_sin);
    cudaGetSymbolAddress((void**)&gbqkv, g_bqkv);

    __half *x16, *o16, *wqkv, *wo, *qkv16;
    cudaGetSymbolAddress((void**)&x16, g_x16);
    cudaGetSymbolAddress((void**)&o16, g_o16);
    cudaGetSymbolAddress((void**)&wqkv, g_wqkv);
    cudaGetSymbolAddress((void**)&wo, g_wo);
    cudaGetSymbolAddress((void**)&qkv16, g_qkv16);

    static cudaStream_t s2 = nullptr;
    static cudaEvent_t eFork = nullptr, eJoin = nullptr;
    static bool attr_set = false;
    if (s2 == nullptr) {
        cudaStreamCreateWithFlags(&s2, cudaStreamNonBlocking);
        cudaEventCreateWithFlags(&eFork, cudaEventDisableTiming);
        cudaEventCreateWithFlags(&eJoin, cudaEventDisableTiming);
    }
    if (!attr_set) {
        cudaFuncSetAttribute(gemm_qkv_rope, cudaFuncAttributeMaxDynamicSharedMemorySize,
                             GSM_TOTAL);
        cudaFuncSetAttribute(gemm_out_bias, cudaFuncAttributeMaxDynamicSharedMemorySize,
                             GSM_TOTAL);
        cudaFuncSetAttribute(flash_tc_v5, cudaFuncAttributeMaxDynamicSharedMemorySize,
                             F5_SMEM_TOTAL);
        attr_set = true;
    }

    const int M = BB * SS;   // 4096
    const int MB = SS;       // rows per batch
    dim3 blk(128);

    // ---- preprocessing on origin stream ----
    rope_table_kernel<<<(SS * 32 + 255) / 256, 256>>>(gc, gs);
    int nx = M * DD;
    cvt_half_kernel<<<(nx + 255) / 256, 256>>>(x, x16, nx);
    pack_wqkv_kernel<<<(DD * NQKV + 255) / 256, 256>>>(Wq, Wk, Wv, bq, bk, bv,
                                                       wqkv, gbqkv);
    cvt_half_kernel<<<(DD * DD + 255) / 256, 256>>>(Wo, wo, DD * DD);

    // ---- fork: batch 1 pipeline on s2 ----
    cudaEventRecord(eFork, 0);
    cudaStreamWaitEvent(s2, eFork, 0);

    // batch 0 (origin stream)
    gemm_qkv_rope<<<dim3(NQKV / 128, MB / 128), blk, GSM_TOTAL>>>(
        x16, wqkv, gbqkv, gc, gs, qkv16, M, NQKV, 1024, 0);
    flash_tc_v5<<<dim3(SS / 64, KHH * 2, 1), 256, F5_SMEM_TOTAL>>>(qkv16, o16, 0);
    gemm_out_bias<<<dim3(1024 / 128, MB / 128), blk, GSM_TOTAL>>>(
        o16, wo, bo, out, M, 1024, 1024, 0);

    // batch 1 (s2)
    gemm_qkv_rope<<<dim3(NQKV / 128, MB / 128), blk, GSM_TOTAL, s2>>>(
        x16, wqkv, gbqkv, gc, gs, qkv16, M, NQKV, 1024, MB);
    flash_tc_v5<<<dim3(SS / 64, KHH * 2, 1), 256, F5_SMEM_TOTAL, s2>>>(qkv16, o16, 1);
    gemm_out_bias<<<dim3(1024 / 128, MB / 128), blk, GSM_TOTAL, s2>>>(
        o16, wo, bo, out, M, 1024, 1024, MB);

    // ---- join ----
    cudaEventRecord(eJoin, s2);
    cudaStreamWaitEvent(0, eJoin, 0);
}